// round 2
// baseline (speedup 1.0000x reference)
#include <cuda_runtime.h>

#define TPB 256
#define RPT 4
#define HID 64
#define BETA_C 0.99f
#define EPS_V 1e-3f
#define LOG_2PI 1.8378770664093453f
#define LOG2E 1.4426950408889634f

// per-block partial sums for the deterministic logp reduction
__device__ float g_part[4096];

__global__ __launch_bounds__(TPB) void mdn_main(
    const float* __restrict__ x, const float* __restrict__ y,
    const float* __restrict__ eps,
    const float* __restrict__ W1, const float* __restrict__ b1,
    const float* __restrict__ W2, const float* __restrict__ b2,
    const float* __restrict__ Wv,
    float* __restrict__ out, int B)
{
    __shared__ float4 sA[HID];  // (W1[0][j], W1[1][j], b1[j], 0)
    __shared__ float4 sW[HID];  // W2 row j (4 outputs)

    int tid = threadIdx.x;
    if (tid < HID) {
        sA[tid] = make_float4(W1[tid], W1[HID + tid], b1[tid], 0.0f);
        sW[tid] = *reinterpret_cast<const float4*>(W2 + 4 * tid);
    }
    __syncthreads();

    // tiny runtime constants -> registers
    const float v00 = __ldg(Wv + 0), v01 = __ldg(Wv + 1);
    const float v10 = __ldg(Wv + 2), v11 = __ldg(Wv + 3);
    const float c0 = __ldg(b2 + 0), c1 = __ldg(b2 + 1);
    const float c2 = __ldg(b2 + 2), c3 = __ldg(b2 + 3);

    const int nth = gridDim.x * TPB;                 // total threads
    const int g   = blockIdx.x * TPB + tid;

    float x0[RPT], x1[RPT];
    float a0[RPT], a1[RPT], a2[RPT], a3[RPT];

    #pragma unroll
    for (int i = 0; i < RPT; i++) {
        int r = g + i * nth;                         // coalesced float2 loads
        float2 xv = *reinterpret_cast<const float2*>(x + 2 * r);
        x0[i] = xv.x; x1[i] = xv.y;
        a0[i] = c0; a1[i] = c1; a2[i] = c2; a3[i] = c3;
    }

    // MLP: j-outer so each weight LDS (broadcast) serves RPT rows
    #pragma unroll 4
    for (int j = 0; j < HID; j++) {
        float4 A = sA[j];
        float4 W = sW[j];
        #pragma unroll
        for (int i = 0; i < RPT; i++) {
            float h = fmaf(A.x, x0[i], fmaf(A.y, x1[i], A.z));
            h = fmaxf(h, 0.0f);                      // relu (alu pipe)
            a0[i] = fmaf(W.x, h, a0[i]);
            a1[i] = fmaf(W.y, h, a1[i]);
            a2[i] = fmaf(W.z, h, a2[i]);
            a3[i] = fmaf(W.w, h, a3[i]);
        }
    }

    float tsum = 0.0f;
    #pragma unroll
    for (int i = 0; i < RPT; i++) {
        int r = g + i * nth;
        float mu0 = a0[i], mu1 = a1[i];
        float h2 = a2[i],  h3 = a3[i];               // log-var heads

        // V(x) and V(mu): ||z Wv||^2 + eps
        float xa = fmaf(x0[i], v00, x1[i] * v10);
        float xb = fmaf(x0[i], v01, x1[i] * v11);
        float Vx = fmaf(xa, xa, fmaf(xb, xb, EPS_V));
        float ma = fmaf(mu0, v00, mu1 * v10);
        float mb = fmaf(mu0, v01, mu1 * v11);
        float Vmu = fmaf(ma, ma, fmaf(mb, mb, EPS_V));

        // (b*Vx - relu(b*Vx - Vmu)) / Vmu  ==  min(b*Vx/Vmu, 1)
        float s = fminf(__fdividef(BETA_C * Vx, Vmu), 1.0f);
        float ms0 = mu0 * s, ms1 = mu1 * s;

        // sqrt(var) = exp2(0.5*log2e*h); 1/var = exp2(-log2e*h); log(var)=h
        float sd0 = exp2f(h2 * (0.5f * LOG2E));
        float sd1 = exp2f(h3 * (0.5f * LOG2E));
        float iv0 = exp2f(h2 * (-LOG2E));
        float iv1 = exp2f(h3 * (-LOG2E));

        float2 ev = *reinterpret_cast<const float2*>(eps + 2 * r);
        float2 yv = *reinterpret_cast<const float2*>(y + 2 * r);

        float2 fx;
        fx.x = fmaf(sd0, ev.x, ms0);
        fx.y = fmaf(sd1, ev.y, ms1);
        *reinterpret_cast<float2*>(out + 2 * r) = fx;

        float d0 = yv.x - ms0, d1 = yv.y - ms1;
        // t' = d^2/var (summed) + h2 + h3 ; the +2*LOG_2PI is deferred
        tsum += fmaf(d0 * d0, iv0, fmaf(d1 * d1, iv1, h2 + h3));
    }

    // warp reduce
    #pragma unroll
    for (int o = 16; o > 0; o >>= 1)
        tsum += __shfl_down_sync(0xFFFFFFFFu, tsum, o);

    __shared__ float wsum[TPB / 32];
    if ((tid & 31) == 0) wsum[tid >> 5] = tsum;
    __syncthreads();
    if (tid == 0) {
        float bs = 0.0f;
        #pragma unroll
        for (int w = 0; w < TPB / 32; w++) bs += wsum[w];
        g_part[blockIdx.x] = bs;
    }
}

__global__ void mdn_reduce(float* __restrict__ out, int B, int nb)
{
    __shared__ float sm[256];
    int tid = threadIdx.x;
    float s = 0.0f;
    for (int i = tid; i < nb; i += 256) s += g_part[i];
    sm[tid] = s;
    __syncthreads();
    #pragma unroll
    for (int o = 128; o > 0; o >>= 1) {
        if (tid < o) sm[tid] += sm[tid + o];
        __syncthreads();
    }
    if (tid == 0) {
        // logp_y = 0.5 * sum(t') + B * LOG_2PI
        out[(size_t)2 * (size_t)B] = fmaf(0.5f, sm[0], (float)B * LOG_2PI);
    }
}

extern "C" void kernel_launch(void* const* d_in, const int* in_sizes, int n_in,
                              void* d_out, int out_size)
{
    const float* x   = (const float*)d_in[0];
    const float* y   = (const float*)d_in[1];
    const float* eps = (const float*)d_in[2];
    const float* W1  = (const float*)d_in[3];
    const float* b1  = (const float*)d_in[4];
    const float* W2  = (const float*)d_in[5];
    const float* b2  = (const float*)d_in[6];
    const float* Wv  = (const float*)d_in[7];
    float* out = (float*)d_out;

    int B = in_sizes[0] / 2;                 // 2,097,152
    int grid = B / (TPB * RPT);              // 2048 (B divisible)

    mdn_main<<<grid, TPB>>>(x, y, eps, W1, b1, W2, b2, Wv, out, B);
    mdn_reduce<<<1, 256>>>(out, B, grid);
}